// round 14
// baseline (speedup 1.0000x reference)
#include <cuda_runtime.h>
#include <math.h>

#define N_CRIT  128
#define N_PAIRS 8128
#define N_TOT   (N_CRIT + N_PAIRS)   // 8256
#define N_VEC4  (N_TOT / 4)          // 2064
#define OCT     (N_VEC4 / 8)         // 258 float4 per eighth-row
#define MIN_W   1e-7f
#define NP4     (N_PAIRS / 4)        // 2032 float4 of wint

// Effective (constrained) weight vector: [wc_eff (128) | wint_eff (8128)]
__device__ __align__(16) float g_w[N_TOT];
__device__ float g_inv_sum;
__device__ volatile int g_ready = 0;  // one-time latch; replays rewrite g_w
                                      // with identical bytes, so stale-flag
                                      // reads are benign and deterministic.

// ---------------------------------------------------------------------------
// Constraint for one pair index. p -> (i, j): p = i*(2*N-1-i)/2 + (j-i-1).
// ---------------------------------------------------------------------------
__device__ __forceinline__ float prep_one(int p, const float* s_wc, float wi) {
    const float disc = sqrtf((float)(65025 - 8 * p));
    int i = (int)((255.0f - disc) * 0.5f);
    int base = i * (2 * N_CRIT - 1 - i) / 2;
    if (base > p)                        { i--; base = i * (2 * N_CRIT - 1 - i) / 2; }
    else if (p - base >= N_CRIT - 1 - i) { i++; base = i * (2 * N_CRIT - 1 - i) / 2; }
    const int j = p - base + i + 1;
    const float lo = fmaxf(-s_wc[i], -s_wc[j]);
    return fmaxf(wi, lo);
}

// Block-0 prep with 256 threads: constraints, g_w, g_inv_sum, then flag.
__device__ __noinline__ void do_prep(const float* __restrict__ wc,
                                     const float* __restrict__ wint,
                                     float* s_wc, float* s_red) {
    const int t = threadIdx.x;

    if (t < N_CRIT) {
        float wce = wc[t];
        if (wce < 0.f) wce = MIN_W;
        s_wc[t] = wce;
        g_w[t]  = wce;
    }
    __syncthreads();

    float sum = (t < N_CRIT) ? s_wc[t] : 0.f;

    const float4* __restrict__ wi4 = reinterpret_cast<const float4*>(wint);
    float4* __restrict__ gw4 = reinterpret_cast<float4*>(g_w + N_CRIT);

    // NP4 = 2032 float4 over 256 threads: 8 rounds
    #pragma unroll
    for (int k = 0; k < 8; k++) {
        const int idx = k * 256 + t;
        if (idx < NP4) {
            const float4 w = wi4[idx];
            const int p = idx * 4;
            float4 v;
            v.x = prep_one(p + 0, s_wc, w.x);
            v.y = prep_one(p + 1, s_wc, w.y);
            v.z = prep_one(p + 2, s_wc, w.z);
            v.w = prep_one(p + 3, s_wc, w.w);
            gw4[idx] = v;
            sum += (v.x + v.y) + (v.z + v.w);
        }
    }

    #pragma unroll
    for (int off = 16; off > 0; off >>= 1)
        sum += __shfl_xor_sync(0xFFFFFFFFu, sum, off);
    if ((t & 31) == 0) s_red[t >> 5] = sum;
    __syncthreads();
    if (t == 0) {
        float v = ((s_red[0] + s_red[1]) + (s_red[2] + s_red[3]))
                + ((s_red[4] + s_red[5]) + (s_red[6] + s_red[7]));
        g_inv_sum = 1.0f / v;
        __threadfence();          // release g_w / g_inv_sum before the flag
        g_ready = 1;
    }
}

// ---------------------------------------------------------------------------
// Fused kernel: block 0 preps then processes row 0; all other blocks spin on
// the latch (thread 0 only), then stream. One block = ONE row; each of the 8
// warps owns one eighth-row (258 float4), strided float4 loads — inner loop
// byte-identical to the R12 measured-best body.
// Epilogue: sigmoid(acc * inv_sum - thr).
// ---------------------------------------------------------------------------
__global__ void __launch_bounds__(256, 8)
choquet_fused_kernel(const float* __restrict__ x,
                     const float* __restrict__ wc,
                     const float* __restrict__ wint,
                     const float* __restrict__ thr,
                     float* __restrict__ out,
                     int rows) {
    __shared__ float s_wc[N_CRIT];   // block 0 prep only
    __shared__ float s_red[8];       // block 0 prep only
    __shared__ float s_part[8];      // per-row reduce

    const int warp = threadIdx.x >> 5;     // 0..7: eighth index within the row
    const int lane = threadIdx.x & 31;
    const int r = blockIdx.x;               // one row per block

    if (blockIdx.x == 0) {
        do_prep(wc, wint, s_wc, s_red);
    } else if (threadIdx.x == 0) {
        while (g_ready == 0) __nanosleep(64);
        __threadfence();          // acquire: order flag read before g_w reads
    }
    __syncthreads();

    const float4* __restrict__ xr = reinterpret_cast<const float4*>(
        x + (size_t)r * N_TOT);
    const float4* __restrict__ w4 = reinterpret_cast<const float4*>(g_w);

    const int base = warp * OCT;             // 0, 258, ..., 1806

    float acc = 0.f;
    // OCT = 258 = 8*32 + 2
    #pragma unroll 4
    for (int k = 0; k < 8; k++) {
        const int i = base + k * 32 + lane;
        const float4 a = xr[i];
        const float4 b = w4[i];
        acc = fmaf(a.x, b.x, acc);
        acc = fmaf(a.y, b.y, acc);
        acc = fmaf(a.z, b.z, acc);
        acc = fmaf(a.w, b.w, acc);
    }
    if (lane < 2) {
        const int i = base + 256 + lane;
        const float4 a = xr[i];
        const float4 b = w4[i];
        acc = fmaf(a.x, b.x, acc);
        acc = fmaf(a.y, b.y, acc);
        acc = fmaf(a.z, b.z, acc);
        acc = fmaf(a.w, b.w, acc);
    }

    // Warp reduction, then cross-warp via smem
    #pragma unroll
    for (int off = 16; off > 0; off >>= 1)
        acc += __shfl_xor_sync(0xFFFFFFFFu, acc, off);
    if (lane == 0) s_part[warp] = acc;
    __syncthreads();

    if (threadIdx.x == 0) {
        const float tot = ((s_part[0] + s_part[1]) + (s_part[2] + s_part[3]))
                        + ((s_part[4] + s_part[5]) + (s_part[6] + s_part[7]));
        const float s = fmaf(tot, g_inv_sum, -thr[0]);
        out[r] = 1.0f / (1.0f + __expf(-s));
    }
}

extern "C" void kernel_launch(void* const* d_in, const int* in_sizes, int n_in,
                              void* d_out, int out_size) {
    const float* x    = (const float*)d_in[0];
    const float* wc   = (const float*)d_in[1];
    const float* wint = (const float*)d_in[2];
    const float* thr  = (const float*)d_in[3];
    float* out = (float*)d_out;

    const int rows = in_sizes[0] / N_TOT;

    choquet_fused_kernel<<<rows, 256>>>(x, wc, wint, thr, out, rows);
}

// round 15
// speedup vs baseline: 1.1445x; 1.1445x over previous
#include <cuda_runtime.h>
#include <math.h>

#define N_CRIT  128
#define N_PAIRS 8128
#define N_TOT   (N_CRIT + N_PAIRS)   // 8256
#define N_VEC4  (N_TOT / 4)          // 2064
#define OCT     (N_VEC4 / 8)         // 258 float4 per eighth-row
#define MIN_W   1e-7f
#define PREP_T  1024
#define NP4     (N_PAIRS / 4)        // 2032 float4 of wint

// Effective (constrained) weight vector: [wc_eff (128) | wint_eff (8128)]
__device__ __align__(16) float g_w[N_TOT];
__device__ float g_inv_sum;

// ---------------------------------------------------------------------------
// Prep (parallel, ~1.5us): apply constraints, build contiguous weight vector,
// compute 1/sum. One block of 1024 threads; wint loaded/stored as float4.
// (i,j) recovered from the flat pair index by triangle inversion.
// ---------------------------------------------------------------------------
__device__ __forceinline__ float prep_one(int p, const float* s_wc, float wi) {
    // p -> (i, j): p = i*(2*N-1-i)/2 + (j-i-1), 2N-1 = 255
    const float disc = sqrtf((float)(65025 - 8 * p));
    int i = (int)((255.0f - disc) * 0.5f);
    int base = i * (2 * N_CRIT - 1 - i) / 2;
    if (base > p)                        { i--; base = i * (2 * N_CRIT - 1 - i) / 2; }
    else if (p - base >= N_CRIT - 1 - i) { i++; base = i * (2 * N_CRIT - 1 - i) / 2; }
    const int j = p - base + i + 1;
    const float lo = fmaxf(-s_wc[i], -s_wc[j]);
    return fmaxf(wi, lo);
}

__global__ void __launch_bounds__(PREP_T)
choquet_prep_kernel(const float* __restrict__ wc,
                    const float* __restrict__ wint) {
    __shared__ float s_wc[N_CRIT];
    __shared__ float s_part[PREP_T / 32];
    const int t = threadIdx.x;

    if (t < N_CRIT) {
        float wce = wc[t];
        if (wce < 0.f) wce = MIN_W;
        s_wc[t] = wce;
        g_w[t]  = wce;
    }
    __syncthreads();

    float sum = (t < N_CRIT) ? s_wc[t] : 0.f;

    const float4* __restrict__ wi4 = reinterpret_cast<const float4*>(wint);
    float4* __restrict__ gw4 = reinterpret_cast<float4*>(g_w + N_CRIT);

    // NP4 = 2032 float4: round 0 covers idx t, round 1 covers idx 1024+t (<2032)
    #pragma unroll
    for (int k = 0; k < 2; k++) {
        const int idx = k * PREP_T + t;
        if (idx < NP4) {
            const float4 w = wi4[idx];
            const int p = idx * 4;
            float4 v;
            v.x = prep_one(p + 0, s_wc, w.x);
            v.y = prep_one(p + 1, s_wc, w.y);
            v.z = prep_one(p + 2, s_wc, w.z);
            v.w = prep_one(p + 3, s_wc, w.w);
            gw4[idx] = v;
            sum += (v.x + v.y) + (v.z + v.w);
        }
    }

    #pragma unroll
    for (int off = 16; off > 0; off >>= 1)
        sum += __shfl_xor_sync(0xFFFFFFFFu, sum, off);
    if ((t & 31) == 0) s_part[t >> 5] = sum;
    __syncthreads();
    if (t < 32) {
        float v = (t < PREP_T / 32) ? s_part[t] : 0.f;
        #pragma unroll
        for (int off = 16; off > 0; off >>= 1)
            v += __shfl_xor_sync(0xFFFFFFFFu, v, off);
        if (t == 0) g_inv_sum = 1.0f / v;
    }
}

// ---------------------------------------------------------------------------
// GEMV: eighth-row work units, fully static, hardware-scheduled (no
// persistence). One block = ONE row; each of the 8 warps owns one eighth-row
// (258 float4), strided float4 loads, unroll 4. Grid = 16384 blocks ->
// ~13.5 waves, tail quantization ~2%. smem reduce across all 8 warps.
// Epilogue: sigmoid(acc * inv_sum - thr).
// ---------------------------------------------------------------------------
__global__ void __launch_bounds__(256, 8)
choquet_gemv_kernel(const float* __restrict__ x,
                    const float* __restrict__ thr,
                    float* __restrict__ out,
                    int rows) {
    __shared__ float s_part[8];

    const int warp = threadIdx.x >> 5;     // 0..7: eighth index within the row
    const int lane = threadIdx.x & 31;
    const int r = blockIdx.x;               // one row per block

    const float4* __restrict__ xr = reinterpret_cast<const float4*>(
        x + (size_t)r * N_TOT);
    const float4* __restrict__ w4 = reinterpret_cast<const float4*>(g_w);

    const int base = warp * OCT;             // 0, 258, 516, ..., 1806

    float acc = 0.f;
    // OCT = 258 = 8*32 + 2
    #pragma unroll 4
    for (int k = 0; k < 8; k++) {
        const int i = base + k * 32 + lane;
        const float4 a = xr[i];
        const float4 b = w4[i];
        acc = fmaf(a.x, b.x, acc);
        acc = fmaf(a.y, b.y, acc);
        acc = fmaf(a.z, b.z, acc);
        acc = fmaf(a.w, b.w, acc);
    }
    if (lane < 2) {
        const int i = base + 256 + lane;
        const float4 a = xr[i];
        const float4 b = w4[i];
        acc = fmaf(a.x, b.x, acc);
        acc = fmaf(a.y, b.y, acc);
        acc = fmaf(a.z, b.z, acc);
        acc = fmaf(a.w, b.w, acc);
    }

    // Warp reduction
    #pragma unroll
    for (int off = 16; off > 0; off >>= 1)
        acc += __shfl_xor_sync(0xFFFFFFFFu, acc, off);
    if (lane == 0) s_part[warp] = acc;
    __syncthreads();

    // Thread 0 finalizes the row
    if (threadIdx.x == 0) {
        const float tot = ((s_part[0] + s_part[1]) + (s_part[2] + s_part[3]))
                        + ((s_part[4] + s_part[5]) + (s_part[6] + s_part[7]));
        const float s = fmaf(tot, g_inv_sum, -thr[0]);
        out[r] = 1.0f / (1.0f + __expf(-s));
    }
}

extern "C" void kernel_launch(void* const* d_in, const int* in_sizes, int n_in,
                              void* d_out, int out_size) {
    const float* x    = (const float*)d_in[0];
    const float* wc   = (const float*)d_in[1];
    const float* wint = (const float*)d_in[2];
    const float* thr  = (const float*)d_in[3];
    float* out = (float*)d_out;

    const int rows = in_sizes[0] / N_TOT;

    choquet_prep_kernel<<<1, PREP_T>>>(wc, wint);

    choquet_gemv_kernel<<<rows, 256>>>(x, thr, out, rows);  // 1 row per block
}

// round 16
// speedup vs baseline: 1.1544x; 1.0086x over previous
#include <cuda_runtime.h>
#include <math.h>

#define N_CRIT  128
#define N_PAIRS 8128
#define N_TOT   (N_CRIT + N_PAIRS)   // 8256
#define N_VEC4  (N_TOT / 4)          // 2064
#define QTR     (N_VEC4 / 4)         // 516 float4 per quarter-row
#define MIN_W   1e-7f
#define PREP_T  1024
#define NP4     (N_PAIRS / 4)        // 2032 float4 of wint

// Effective (constrained) weight vector: [wc_eff (128) | wint_eff (8128)]
__device__ __align__(16) float g_w[N_TOT];
__device__ float g_inv_sum;

// ---------------------------------------------------------------------------
// Prep (parallel, ~1.5us): apply constraints, build contiguous weight vector,
// compute 1/sum. One block of 1024 threads; wint loaded/stored as float4.
// (i,j) recovered from the flat pair index by triangle inversion.
// ---------------------------------------------------------------------------
__device__ __forceinline__ float prep_one(int p, const float* s_wc, float wi) {
    // p -> (i, j): p = i*(2*N-1-i)/2 + (j-i-1), 2N-1 = 255
    const float disc = sqrtf((float)(65025 - 8 * p));
    int i = (int)((255.0f - disc) * 0.5f);
    int base = i * (2 * N_CRIT - 1 - i) / 2;
    if (base > p)                        { i--; base = i * (2 * N_CRIT - 1 - i) / 2; }
    else if (p - base >= N_CRIT - 1 - i) { i++; base = i * (2 * N_CRIT - 1 - i) / 2; }
    const int j = p - base + i + 1;
    const float lo = fmaxf(-s_wc[i], -s_wc[j]);
    return fmaxf(wi, lo);
}

__global__ void __launch_bounds__(PREP_T)
choquet_prep_kernel(const float* __restrict__ wc,
                    const float* __restrict__ wint) {
    __shared__ float s_wc[N_CRIT];
    __shared__ float s_part[PREP_T / 32];
    const int t = threadIdx.x;

    if (t < N_CRIT) {
        float wce = wc[t];
        if (wce < 0.f) wce = MIN_W;
        s_wc[t] = wce;
        g_w[t]  = wce;
    }
    __syncthreads();

    float sum = (t < N_CRIT) ? s_wc[t] : 0.f;

    const float4* __restrict__ wi4 = reinterpret_cast<const float4*>(wint);
    float4* __restrict__ gw4 = reinterpret_cast<float4*>(g_w + N_CRIT);

    // NP4 = 2032 float4: round 0 covers idx t, round 1 covers idx 1024+t (<2032)
    #pragma unroll
    for (int k = 0; k < 2; k++) {
        const int idx = k * PREP_T + t;
        if (idx < NP4) {
            const float4 w = wi4[idx];
            const int p = idx * 4;
            float4 v;
            v.x = prep_one(p + 0, s_wc, w.x);
            v.y = prep_one(p + 1, s_wc, w.y);
            v.z = prep_one(p + 2, s_wc, w.z);
            v.w = prep_one(p + 3, s_wc, w.w);
            gw4[idx] = v;
            sum += (v.x + v.y) + (v.z + v.w);
        }
    }

    #pragma unroll
    for (int off = 16; off > 0; off >>= 1)
        sum += __shfl_xor_sync(0xFFFFFFFFu, sum, off);
    if ((t & 31) == 0) s_part[t >> 5] = sum;
    __syncthreads();
    if (t < 32) {
        float v = (t < PREP_T / 32) ? s_part[t] : 0.f;
        #pragma unroll
        for (int off = 16; off > 0; off >>= 1)
            v += __shfl_xor_sync(0xFFFFFFFFu, v, off);
        if (t == 0) g_inv_sum = 1.0f / v;
    }
}

// ---------------------------------------------------------------------------
// GEMV: 128-thread blocks, one row per block, quarter-row (516 float4) per
// warp — R6's best-measured warp workload with a narrower (4-warp) barrier
// and finer block-scheduler granularity (16 blocks/SM). Strided float4
// loads, unroll 4. smem reduce across the 4 warps.
// Epilogue: sigmoid(acc * inv_sum - thr).
// ---------------------------------------------------------------------------
__global__ void __launch_bounds__(128, 16)
choquet_gemv_kernel(const float* __restrict__ x,
                    const float* __restrict__ thr,
                    float* __restrict__ out,
                    int rows) {
    __shared__ float s_part[4];

    const int warp = threadIdx.x >> 5;     // 0..3: quarter index within row
    const int lane = threadIdx.x & 31;
    const int r = blockIdx.x;               // one row per block

    const float4* __restrict__ xr = reinterpret_cast<const float4*>(
        x + (size_t)r * N_TOT);
    const float4* __restrict__ w4 = reinterpret_cast<const float4*>(g_w);

    const int base = warp * QTR;             // 0, 516, 1032, 1548

    float acc = 0.f;
    // QTR = 516 = 16*32 + 4
    #pragma unroll 4
    for (int k = 0; k < 16; k++) {
        const int i = base + k * 32 + lane;
        const float4 a = xr[i];
        const float4 b = w4[i];
        acc = fmaf(a.x, b.x, acc);
        acc = fmaf(a.y, b.y, acc);
        acc = fmaf(a.z, b.z, acc);
        acc = fmaf(a.w, b.w, acc);
    }
    if (lane < 4) {
        const int i = base + 512 + lane;
        const float4 a = xr[i];
        const float4 b = w4[i];
        acc = fmaf(a.x, b.x, acc);
        acc = fmaf(a.y, b.y, acc);
        acc = fmaf(a.z, b.z, acc);
        acc = fmaf(a.w, b.w, acc);
    }

    // Warp reduction
    #pragma unroll
    for (int off = 16; off > 0; off >>= 1)
        acc += __shfl_xor_sync(0xFFFFFFFFu, acc, off);
    if (lane == 0) s_part[warp] = acc;
    __syncthreads();

    // Thread 0 finalizes the row
    if (threadIdx.x == 0) {
        const float tot = (s_part[0] + s_part[1]) + (s_part[2] + s_part[3]);
        const float s = fmaf(tot, g_inv_sum, -thr[0]);
        out[r] = 1.0f / (1.0f + __expf(-s));
    }
}

extern "C" void kernel_launch(void* const* d_in, const int* in_sizes, int n_in,
                              void* d_out, int out_size) {
    const float* x    = (const float*)d_in[0];
    const float* wc   = (const float*)d_in[1];
    const float* wint = (const float*)d_in[2];
    const float* thr  = (const float*)d_in[3];
    float* out = (float*)d_out;

    const int rows = in_sizes[0] / N_TOT;

    choquet_prep_kernel<<<1, PREP_T>>>(wc, wint);

    choquet_gemv_kernel<<<rows, 128>>>(x, thr, out, rows);  // 1 row per block
}